// round 2
// baseline (speedup 1.0000x reference)
#include <cuda_runtime.h>
#include <math.h>

#define H 160           // B*G = 4*40 heads
#define C 13
#define T 1024
#define F 513           // rfft bins
#define NSIG (H * C)    // 2080 signals

// ---------------- scratch (device globals: allowed; no runtime alloc) ------
__device__ float2 d_W[512];        // twiddles exp(-2*pi*i*k/1024)
__device__ float2 d_X[H * C * F];  // spectrum, layout [head][c][f]
__device__ float2 d_Q[H * C * F];
__device__ float2 d_K[H * C * F];
__device__ float2 d_V[H * C * F];
__device__ float2 d_O[H * C * F];

// ---------------- twiddle init (double trig for precision) -----------------
__global__ void init_twiddles() {
    int k = threadIdx.x;  // 0..511
    double ang = -2.0 * 3.14159265358979323846 * (double)k / 1024.0;
    d_W[k] = make_float2((float)cos(ang), (float)sin(ang));
}

// ---------------- shared radix-2 DIT FFT core (1024 pts, 512 threads) ------
__device__ __forceinline__ void fft_stages(float2* a, bool inverse) {
    int tid = threadIdx.x;
#pragma unroll
    for (int s = 1; s <= 10; ++s) {
        __syncthreads();
        int half = 1 << (s - 1);
        int k = tid & (half - 1);
        int i0 = ((tid >> (s - 1)) << s) + k;
        float2 w = d_W[k << (10 - s)];
        if (inverse) w.y = -w.y;
        float2 u = a[i0];
        float2 v = a[i0 + half];
        float tr = w.x * v.x - w.y * v.y;
        float ti = w.x * v.y + w.y * v.x;
        a[i0]        = make_float2(u.x + tr, u.y + ti);
        a[i0 + half] = make_float2(u.x - tr, u.y - ti);
    }
    __syncthreads();
}

// ---------------- forward rfft: x[sig][0..1023] -> d_X[sig][0..512] --------
__global__ void fft_forward(const float* __restrict__ x) {
    __shared__ float2 a[1024];
    int sig = blockIdx.x;   // head*13 + c
    int tid = threadIdx.x;  // 0..511
    const float* xp = x + sig * 1024;
    a[__brev(tid) >> 22]       = make_float2(xp[tid], 0.f);
    a[__brev(tid + 512) >> 22] = make_float2(xp[tid + 512], 0.f);
    fft_stages(a, false);
    float2* Xp = d_X + sig * F;
    Xp[tid] = a[tid];
    if (tid == 0) Xp[512] = a[512];
}

// ---------------- QKV: [head][c][f] = sum_cin X[head][cin][f] * W[cin][c] --
__global__ void qkv_kernel(const float* __restrict__ wq,
                           const float* __restrict__ wk,
                           const float* __restrict__ wv) {
    __shared__ float ws[3][169];
    int tid = threadIdx.x;
    if (tid < 169) {
        ws[0][tid] = wq[tid];
        ws[1][tid] = wk[tid];
        ws[2][tid] = wv[tid];
    }
    __syncthreads();
    int head = blockIdx.y;
    int f = blockIdx.x * blockDim.x + tid;
    if (f >= F) return;
    float xr[13], xi[13];
#pragma unroll
    for (int c = 0; c < 13; ++c) {
        float2 v = d_X[(head * 13 + c) * F + f];
        xr[c] = v.x;
        xi[c] = v.y;
    }
#pragma unroll 1
    for (int co = 0; co < 13; ++co) {
        float qr = 0.f, qi = 0.f, kr = 0.f, ki = 0.f, vr = 0.f, vi = 0.f;
#pragma unroll
        for (int ci = 0; ci < 13; ++ci) {
            float a = ws[0][ci * 13 + co];
            qr = fmaf(xr[ci], a, qr); qi = fmaf(xi[ci], a, qi);
            float b = ws[1][ci * 13 + co];
            kr = fmaf(xr[ci], b, kr); ki = fmaf(xi[ci], b, ki);
            float g = ws[2][ci * 13 + co];
            vr = fmaf(xr[ci], g, vr); vi = fmaf(xi[ci], g, vi);
        }
        int o = (head * 13 + co) * F + f;
        d_Q[o] = make_float2(qr, qi);
        d_K[o] = make_float2(kr, ki);
        d_V[o] = make_float2(vr, vi);
    }
}

// ---------------- attention: 1 CTA = 16 rows of one head --------------------
#define TR 16
#define KT 128
#define NTILE 5  // ceil(513/128)

__global__ __launch_bounds__(512) void attn_kernel() {
    __shared__ float2 q_sm[TR * 13];     // 1664 B
    __shared__ float  s_sm[TR * F];      // 32832 B
    __shared__ float2 kv_sm[13 * KT];    // 13312 B   (total 47808 B < 48 KB)

    int head = blockIdx.y;
    int tid = threadIdx.x, lane = tid & 31, w = tid >> 5;
    int f = blockIdx.x * TR + w;
    bool act = f < F;

    // load Q tile
    for (int i = tid; i < TR * 13; i += 512) {
        int r = i / 13, c = i % 13;
        int fr = blockIdx.x * TR + r;
        q_sm[i] = (fr < F) ? d_Q[(head * 13 + c) * F + fr] : make_float2(0.f, 0.f);
    }
    __syncthreads();

    float2 qv[13];
    if (act) {
#pragma unroll
        for (int c = 0; c < 13; ++c) qv[c] = q_sm[w * 13 + c];
    }

    // pass 1: scores = |q . k^T|  (stream K tiles through smem)
    float m = -1e30f;
    for (int tile = 0; tile < NTILE; ++tile) {
        int base = tile * KT;
        __syncthreads();
        for (int i = tid; i < 13 * KT; i += 512) {
            int c = i / KT, fl = i % KT;
            int f2 = base + fl;
            kv_sm[i] = (f2 < F) ? d_K[(head * 13 + c) * F + f2] : make_float2(0.f, 0.f);
        }
        __syncthreads();
        if (act) {
            for (int fl = lane; fl < KT; fl += 32) {
                int f2 = base + fl;
                if (f2 >= F) break;
                float sr = 0.f, si = 0.f;
#pragma unroll
                for (int c = 0; c < 13; ++c) {
                    float2 k = kv_sm[c * KT + fl];
                    sr = fmaf(qv[c].x, k.x, sr);
                    sr = fmaf(-qv[c].y, k.y, sr);
                    si = fmaf(qv[c].x, k.y, si);
                    si = fmaf(qv[c].y, k.x, si);
                }
                float sc = sqrtf(sr * sr + si * si);
                s_sm[w * F + f2] = sc;
                m = fmaxf(m, sc);
            }
        }
    }

    // row softmax (per-warp, no cross-warp deps)
#pragma unroll
    for (int o = 16; o; o >>= 1) m = fmaxf(m, __shfl_xor_sync(0xffffffffu, m, o));
    float l = 0.f;
    if (act) {
        for (int f2 = lane; f2 < F; f2 += 32) {
            float p = __expf(s_sm[w * F + f2] - m);
            s_sm[w * F + f2] = p;
            l += p;
        }
    }
#pragma unroll
    for (int o = 16; o; o >>= 1) l += __shfl_xor_sync(0xffffffffu, l, o);
    float inv = 1.f / l;

    // pass 2: out = P @ V (stream V tiles)
    float ar[13], ai[13];
#pragma unroll
    for (int c = 0; c < 13; ++c) { ar[c] = 0.f; ai[c] = 0.f; }
    for (int tile = 0; tile < NTILE; ++tile) {
        int base = tile * KT;
        __syncthreads();
        for (int i = tid; i < 13 * KT; i += 512) {
            int c = i / KT, fl = i % KT;
            int f2 = base + fl;
            kv_sm[i] = (f2 < F) ? d_V[(head * 13 + c) * F + f2] : make_float2(0.f, 0.f);
        }
        __syncthreads();
        if (act) {
            for (int fl = lane; fl < KT; fl += 32) {
                int f2 = base + fl;
                if (f2 >= F) break;
                float p = s_sm[w * F + f2];
#pragma unroll
                for (int c = 0; c < 13; ++c) {
                    float2 v = kv_sm[c * KT + fl];
                    ar[c] = fmaf(p, v.x, ar[c]);
                    ai[c] = fmaf(p, v.y, ai[c]);
                }
            }
        }
    }

    // warp-reduce 13 complex accumulators, lane 0 writes
#pragma unroll
    for (int c = 0; c < 13; ++c) {
#pragma unroll
        for (int o = 16; o; o >>= 1) {
            ar[c] += __shfl_xor_sync(0xffffffffu, ar[c], o);
            ai[c] += __shfl_xor_sync(0xffffffffu, ai[c], o);
        }
    }
    if (act && lane == 0) {
#pragma unroll
        for (int c = 0; c < 13; ++c)
            d_O[(head * 13 + c) * F + f] = make_float2(ar[c] * inv, ai[c] * inv);
    }
}

// ---------------- irfft: Hermitian extend + inverse FFT, real part ---------
__global__ void ifft_kernel(float* __restrict__ out) {
    __shared__ float2 a[1024];
    int sig = blockIdx.x;
    int tid = threadIdx.x;  // 0..511
    const float2* Op = d_O + sig * F;
    float2 o = Op[tid];
    a[__brev(tid) >> 22] = o;
    if (tid > 0) a[__brev(1024 - tid) >> 22] = make_float2(o.x, -o.y);
    if (tid == 0) a[__brev(512) >> 22] = Op[512];
    fft_stages(a, true);
    const float scale = 1.0f / 1024.0f;
    float* op = out + sig * 1024;
    op[tid]       = a[tid].x * scale;
    op[tid + 512] = a[tid + 512].x * scale;
}

// ---------------- launcher --------------------------------------------------
extern "C" void kernel_launch(void* const* d_in, const int* in_sizes, int n_in,
                              void* d_out, int out_size) {
    const float* x  = (const float*)d_in[0];
    const float* wq = (const float*)d_in[1];
    const float* wk = (const float*)d_in[2];
    const float* wv = (const float*)d_in[3];
    float* out = (float*)d_out;

    init_twiddles<<<1, 512>>>();
    fft_forward<<<NSIG, 512>>>(x);
    qkv_kernel<<<dim3(3, H), 256>>>(wq, wk, wv);
    attn_kernel<<<dim3((F + TR - 1) / TR, H), 512>>>();
    ifft_kernel<<<NSIG, 512>>>(out);
}

// round 3
// speedup vs baseline: 1.0040x; 1.0040x over previous
#include <cuda_runtime.h>
#include <math.h>

#define H 160           // B*G = 4*40 heads
#define C 13
#define T 1024
#define F 513           // rfft bins
#define NSIG (H * C)    // 2080 signals

// ---------------- scratch (device globals: allowed; no runtime alloc) ------
__device__ float2 d_W[512];        // twiddles exp(-2*pi*i*k/1024)
__device__ float2 d_X[H * C * F];  // spectrum, layout [head][c][f]
__device__ float2 d_Q[H * C * F];
__device__ float2 d_K[H * C * F];
__device__ float2 d_V[H * C * F];
__device__ float2 d_O[H * C * F];

// ---------------- twiddle init (double trig for precision) -----------------
__global__ void init_twiddles() {
    int k = threadIdx.x;  // 0..511
    double ang = -2.0 * 3.14159265358979323846 * (double)k / 1024.0;
    d_W[k] = make_float2((float)cos(ang), (float)sin(ang));
}

// ---------------- shared radix-2 DIT FFT core (1024 pts, 512 threads) ------
__device__ __forceinline__ void fft_stages(float2* a, bool inverse) {
    int tid = threadIdx.x;
#pragma unroll
    for (int s = 1; s <= 10; ++s) {
        __syncthreads();
        int half = 1 << (s - 1);
        int k = tid & (half - 1);
        int i0 = ((tid >> (s - 1)) << s) + k;
        float2 w = d_W[k << (10 - s)];
        if (inverse) w.y = -w.y;
        float2 u = a[i0];
        float2 v = a[i0 + half];
        float tr = w.x * v.x - w.y * v.y;
        float ti = w.x * v.y + w.y * v.x;
        a[i0]        = make_float2(u.x + tr, u.y + ti);
        a[i0 + half] = make_float2(u.x - tr, u.y - ti);
    }
    __syncthreads();
}

// ---------------- forward rfft: x[sig][0..1023] -> d_X[sig][0..512] --------
__global__ void fft_forward(const float* __restrict__ x) {
    __shared__ float2 a[1024];
    int sig = blockIdx.x;   // head*13 + c
    int tid = threadIdx.x;  // 0..511
    const float* xp = x + sig * 1024;
    a[__brev(tid) >> 22]       = make_float2(xp[tid], 0.f);
    a[__brev(tid + 512) >> 22] = make_float2(xp[tid + 512], 0.f);
    fft_stages(a, false);
    float2* Xp = d_X + sig * F;
    Xp[tid] = a[tid];
    if (tid == 0) Xp[512] = a[512];
}

// ---------------- QKV: [head][c][f] = sum_cin X[head][cin][f] * W[cin][c] --
__global__ void qkv_kernel(const float* __restrict__ wq,
                           const float* __restrict__ wk,
                           const float* __restrict__ wv) {
    __shared__ float ws[3][169];
    int tid = threadIdx.x;
    if (tid < 169) {
        ws[0][tid] = wq[tid];
        ws[1][tid] = wk[tid];
        ws[2][tid] = wv[tid];
    }
    __syncthreads();
    int head = blockIdx.y;
    int f = blockIdx.x * blockDim.x + tid;
    if (f >= F) return;
    float xr[13], xi[13];
#pragma unroll
    for (int c = 0; c < 13; ++c) {
        float2 v = d_X[(head * 13 + c) * F + f];
        xr[c] = v.x;
        xi[c] = v.y;
    }
#pragma unroll 1
    for (int co = 0; co < 13; ++co) {
        float qr = 0.f, qi = 0.f, kr = 0.f, ki = 0.f, vr = 0.f, vi = 0.f;
#pragma unroll
        for (int ci = 0; ci < 13; ++ci) {
            float a = ws[0][ci * 13 + co];
            qr = fmaf(xr[ci], a, qr); qi = fmaf(xi[ci], a, qi);
            float b = ws[1][ci * 13 + co];
            kr = fmaf(xr[ci], b, kr); ki = fmaf(xi[ci], b, ki);
            float g = ws[2][ci * 13 + co];
            vr = fmaf(xr[ci], g, vr); vi = fmaf(xi[ci], g, vi);
        }
        int o = (head * 13 + co) * F + f;
        d_Q[o] = make_float2(qr, qi);
        d_K[o] = make_float2(kr, ki);
        d_V[o] = make_float2(vr, vi);
    }
}

// ---------------- attention: 1 CTA = 16 rows of one head --------------------
#define TR 16
#define KT 128
#define NTILE 5  // ceil(513/128)

__global__ __launch_bounds__(512) void attn_kernel() {
    __shared__ float2 q_sm[TR * 13];     // 1664 B
    __shared__ float  s_sm[TR * F];      // 32832 B
    __shared__ float2 kv_sm[13 * KT];    // 13312 B   (total 47808 B < 48 KB)

    int head = blockIdx.y;
    int tid = threadIdx.x, lane = tid & 31, w = tid >> 5;
    int f = blockIdx.x * TR + w;
    bool act = f < F;

    // load Q tile
    for (int i = tid; i < TR * 13; i += 512) {
        int r = i / 13, c = i % 13;
        int fr = blockIdx.x * TR + r;
        q_sm[i] = (fr < F) ? d_Q[(head * 13 + c) * F + fr] : make_float2(0.f, 0.f);
    }
    __syncthreads();

    float2 qv[13];
    if (act) {
#pragma unroll
        for (int c = 0; c < 13; ++c) qv[c] = q_sm[w * 13 + c];
    }

    // pass 1: scores = |q . k^T|  (stream K tiles through smem)
    float m = -1e30f;
    for (int tile = 0; tile < NTILE; ++tile) {
        int base = tile * KT;
        __syncthreads();
        for (int i = tid; i < 13 * KT; i += 512) {
            int c = i / KT, fl = i % KT;
            int f2 = base + fl;
            kv_sm[i] = (f2 < F) ? d_K[(head * 13 + c) * F + f2] : make_float2(0.f, 0.f);
        }
        __syncthreads();
        if (act) {
            for (int fl = lane; fl < KT; fl += 32) {
                int f2 = base + fl;
                if (f2 >= F) break;
                float sr = 0.f, si = 0.f;
#pragma unroll
                for (int c = 0; c < 13; ++c) {
                    float2 k = kv_sm[c * KT + fl];
                    sr = fmaf(qv[c].x, k.x, sr);
                    sr = fmaf(-qv[c].y, k.y, sr);
                    si = fmaf(qv[c].x, k.y, si);
                    si = fmaf(qv[c].y, k.x, si);
                }
                float sc = sqrtf(sr * sr + si * si);
                s_sm[w * F + f2] = sc;
                m = fmaxf(m, sc);
            }
        }
    }

    // row softmax (per-warp, no cross-warp deps)
#pragma unroll
    for (int o = 16; o; o >>= 1) m = fmaxf(m, __shfl_xor_sync(0xffffffffu, m, o));
    float l = 0.f;
    if (act) {
        for (int f2 = lane; f2 < F; f2 += 32) {
            float p = __expf(s_sm[w * F + f2] - m);
            s_sm[w * F + f2] = p;
            l += p;
        }
    }
#pragma unroll
    for (int o = 16; o; o >>= 1) l += __shfl_xor_sync(0xffffffffu, l, o);
    float inv = 1.f / l;

    // pass 2: out = P @ V (stream V tiles)
    float ar[13], ai[13];
#pragma unroll
    for (int c = 0; c < 13; ++c) { ar[c] = 0.f; ai[c] = 0.f; }
    for (int tile = 0; tile < NTILE; ++tile) {
        int base = tile * KT;
        __syncthreads();
        for (int i = tid; i < 13 * KT; i += 512) {
            int c = i / KT, fl = i % KT;
            int f2 = base + fl;
            kv_sm[i] = (f2 < F) ? d_V[(head * 13 + c) * F + f2] : make_float2(0.f, 0.f);
        }
        __syncthreads();
        if (act) {
            for (int fl = lane; fl < KT; fl += 32) {
                int f2 = base + fl;
                if (f2 >= F) break;
                float p = s_sm[w * F + f2];
#pragma unroll
                for (int c = 0; c < 13; ++c) {
                    float2 v = kv_sm[c * KT + fl];
                    ar[c] = fmaf(p, v.x, ar[c]);
                    ai[c] = fmaf(p, v.y, ai[c]);
                }
            }
        }
    }

    // warp-reduce 13 complex accumulators, lane 0 writes
#pragma unroll
    for (int c = 0; c < 13; ++c) {
#pragma unroll
        for (int o = 16; o; o >>= 1) {
            ar[c] += __shfl_xor_sync(0xffffffffu, ar[c], o);
            ai[c] += __shfl_xor_sync(0xffffffffu, ai[c], o);
        }
    }
    if (act && lane == 0) {
#pragma unroll
        for (int c = 0; c < 13; ++c)
            d_O[(head * 13 + c) * F + f] = make_float2(ar[c] * inv, ai[c] * inv);
    }
}

// ---------------- irfft: Hermitian extend + inverse FFT, real part ---------
__global__ void ifft_kernel(float* __restrict__ out) {
    __shared__ float2 a[1024];
    int sig = blockIdx.x;
    int tid = threadIdx.x;  // 0..511
    const float2* Op = d_O + sig * F;
    float2 o = Op[tid];
    a[__brev(tid) >> 22] = o;
    if (tid > 0) a[__brev(1024 - tid) >> 22] = make_float2(o.x, -o.y);
    if (tid == 0) a[__brev(512) >> 22] = Op[512];
    fft_stages(a, true);
    const float scale = 1.0f / 1024.0f;
    float* op = out + sig * 1024;
    op[tid]       = a[tid].x * scale;
    op[tid + 512] = a[tid + 512].x * scale;
}

// ---------------- launcher --------------------------------------------------
extern "C" void kernel_launch(void* const* d_in, const int* in_sizes, int n_in,
                              void* d_out, int out_size) {
    const float* x  = (const float*)d_in[0];
    const float* wq = (const float*)d_in[1];
    const float* wk = (const float*)d_in[2];
    const float* wv = (const float*)d_in[3];
    float* out = (float*)d_out;

    init_twiddles<<<1, 512>>>();
    fft_forward<<<NSIG, 512>>>(x);
    qkv_kernel<<<dim3(3, H), 256>>>(wq, wk, wv);
    attn_kernel<<<dim3((F + TR - 1) / TR, H), 512>>>();
    ifft_kernel<<<NSIG, 512>>>(out);
}